// round 2
// baseline (speedup 1.0000x reference)
#include <cuda_runtime.h>
#include <cstdint>
#include <cstddef>

// Bihomogeneous_k3 — row-per-lane, fully unrolled compile-time column schedule.
// 35 complex monomials held in registers; outputs transposed through a
// bank-conflict-free smem tile for coalesced streaming stores.

#define NVAR 5
#define NM 35
#define NCOL 1225
#define ROWS 32          // rows per warp (one per lane)
#define CHUNK 64         // columns per transpose chunk
#define NCHUNK 19        // 19*64 = 1216 full-chunk columns
#define TAIL 9           // 1225 - 1216
#define STRIDE 65        // tile row stride (odd -> conflict-free columns)
#define WPB 4            // warps per block

struct PQ { int p, q, im; };
__host__ __device__ constexpr PQ pq_of(int c) {
    int idx = 0;
    for (int p = 0; p < NM; p++)
        for (int q = p; q < NM; q++) {
            if (idx == c) return PQ{p, q, 0};
            idx++;
        }
    for (int p = 0; p < NM; p++)
        for (int q = p + 1; q < NM; q++) {
            if (idx == c) return PQ{p, q, 1};
            idx++;
        }
    return PQ{0, 0, 0};
}

struct IJK { int i, j, k; };
__host__ __device__ constexpr IJK ijk_of(int m) {
    int idx = 0;
    for (int i = 0; i < NVAR; i++)
        for (int j = i; j < NVAR; j++)
            for (int k = j; k < NVAR; k++) {
                if (idx == m) return IJK{i, j, k};
                idx++;
            }
    return IJK{0, 0, 0};
}

template<int... I> struct iseq {};
template<int N, int... I> struct make_iseq : make_iseq<N - 1, N - 1, I...> {};
template<int... I> struct make_iseq<0, I...> { using type = iseq<I...>; };

// ---- stage 1: monomials into registers (compile-time indices) ----
template<int M>
__device__ __forceinline__ void mono1(const float (&zr)[NVAR], const float (&zi)[NVAR],
                                      float (&zzr)[NM], float (&zzi)[NM]) {
    constexpr IJK t = ijk_of(M);
    const float ar = zr[t.i], ai = zi[t.i];
    const float br = zr[t.j], bi = zi[t.j];
    const float cr = zr[t.k], ci = zi[t.k];
    const float tr = ar * br - ai * bi;
    const float ti = ar * bi + ai * br;
    zzr[M] = tr * cr - ti * ci;
    zzi[M] = tr * ci + ti * cr;
}
template<int... M>
__device__ __forceinline__ void monos(iseq<M...>, const float (&zr)[NVAR], const float (&zi)[NVAR],
                                      float (&zzr)[NM], float (&zzi)[NM]) {
    (mono1<M>(zr, zi, zzr, zzi), ...);
}

// ---- stage 2: one output column, compile-time (p,q,im) ----
template<int C>
__device__ __forceinline__ float colval(const float (&zzr)[NM], const float (&zzi)[NM]) {
    constexpr PQ t = pq_of(C);
    if constexpr (t.im != 0)
        return zzi[t.p] * zzr[t.q] - zzr[t.p] * zzi[t.q];   // im(zz_p * conj(zz_q))
    else
        return zzr[t.p] * zzr[t.q] + zzi[t.p] * zzi[t.q];   // re(zz_p * conj(zz_q))
}

template<int C0, int... CC>
__device__ __forceinline__ void chunk_cols(iseq<CC...>,
                                           const float (&zzr)[NM], const float (&zzi)[NM],
                                           float* tl /* &tile[lane*STRIDE] */) {
    ((tl[CC] = colval<C0 + CC>(zzr, zzi)), ...);
}

// ---- one 64-column chunk: compute -> transpose tile -> coalesced flush ----
template<int CH>
__device__ __forceinline__ void do_chunk(const float (&zzr)[NM], const float (&zzi)[NM],
                                         float* tl, const float* tile_w,
                                         float* __restrict__ out,
                                         int rowbase, int lane, int B) {
    constexpr int C0 = CH * CHUNK;
    chunk_cols<C0>(typename make_iseq<CHUNK>::type{}, zzr, zzi, tl);
    __syncwarp();
    float* obase = out + (size_t)rowbase * NCOL + C0 + lane;
    if (rowbase + ROWS <= B) {
        #pragma unroll
        for (int r = 0; r < ROWS; r++) {
            __stcs(obase + (size_t)r * NCOL,      tile_w[r * STRIDE + lane]);
            __stcs(obase + (size_t)r * NCOL + 32, tile_w[r * STRIDE + 32 + lane]);
        }
    } else {
        #pragma unroll
        for (int r = 0; r < ROWS; r++) {
            if (rowbase + r < B) {
                __stcs(obase + (size_t)r * NCOL,      tile_w[r * STRIDE + lane]);
                __stcs(obase + (size_t)r * NCOL + 32, tile_w[r * STRIDE + 32 + lane]);
            }
        }
    }
    __syncwarp();
}

__device__ __forceinline__ void do_tail(const float (&zzr)[NM], const float (&zzi)[NM],
                                        float* tl, const float* tile_w,
                                        float* __restrict__ out,
                                        int rowbase, int lane, int B) {
    constexpr int C0 = NCHUNK * CHUNK;   // 1216
    chunk_cols<C0>(typename make_iseq<TAIL>::type{}, zzr, zzi, tl);
    __syncwarp();
    float* obase = out + (size_t)rowbase * NCOL + C0 + lane;
    #pragma unroll
    for (int r = 0; r < ROWS; r++) {
        if (lane < TAIL && rowbase + r < B)
            __stcs(obase + (size_t)r * NCOL, tile_w[r * STRIDE + lane]);
    }
}

template<int... CH>
__device__ __forceinline__ void all_chunks(iseq<CH...>,
                                           const float (&zzr)[NM], const float (&zzi)[NM],
                                           float* tl, const float* tile_w,
                                           float* __restrict__ out,
                                           int rowbase, int lane, int B) {
    (do_chunk<CH>(zzr, zzi, tl, tile_w, out, rowbase, lane, B), ...);
}

__global__ void __launch_bounds__(WPB * 32)
bihom_k3_kernel(const float* __restrict__ z_re,
                const float* __restrict__ z_im,
                float* __restrict__ out, int B)
{
    __shared__ float tile[WPB][ROWS * STRIDE];

    const int warp = threadIdx.x >> 5;
    const int lane = threadIdx.x & 31;
    const int rowbase = (blockIdx.x * WPB + warp) * ROWS;
    const int row = rowbase + lane;
    const bool valid = row < B;

    // load this lane's row (5 complex values) into registers
    float zr[NVAR], zi[NVAR];
    #pragma unroll
    for (int v = 0; v < NVAR; v++) {
        zr[v] = valid ? z_re[row * NVAR + v] : 0.0f;
        zi[v] = valid ? z_im[row * NVAR + v] : 0.0f;
    }

    // 35 complex monomials, all in registers
    float zzr[NM], zzi[NM];
    monos(typename make_iseq<NM>::type{}, zr, zi, zzr, zzi);

    float* tl = &tile[warp][lane * STRIDE];
    const float* tile_w = &tile[warp][0];

    all_chunks(typename make_iseq<NCHUNK>::type{}, zzr, zzi, tl, tile_w, out, rowbase, lane, B);
    do_tail(zzr, zzi, tl, tile_w, out, rowbase, lane, B);
}

extern "C" void kernel_launch(void* const* d_in, const int* in_sizes, int n_in,
                              void* d_out, int out_size) {
    const float* z_re = (const float*)d_in[0];
    const float* z_im = (const float*)d_in[1];
    float* out = (float*)d_out;
    const int B = in_sizes[0] / NVAR;
    const int rows_per_block = WPB * ROWS;                       // 128
    const int grid = (B + rows_per_block - 1) / rows_per_block;  // 1024 for B=131072
    bihom_k3_kernel<<<grid, WPB * 32>>>(z_re, z_im, out, B);
}

// round 3
// speedup vs baseline: 1.7658x; 1.7658x over previous
#include <cuda_runtime.h>
#include <cstdint>
#include <cstddef>

// Bihomogeneous_k3 — warp-per-row, fused re+im per pair.
// One (a,b) smem operand fetch produces both re(zz_p conj zz_q) -> col s
// and im -> col 630 + s - p - 1 (strict pairs only). Halves operand traffic
// per output byte vs computing the two halves in separate passes.

#define NVAR 5
#define NM 35
#define NPAIR 630      // full pairs p<=q (re columns 0..629)
#define NCOL 1225
#define WPB 8          // warps per block
#define NGRP 20        // ceil(630/32)

struct Tab {
    uchar2 pq[NGRP * 32];   // (p, q) per full-pair index, padded
    ushort ijk[40];         // i | j<<4 | k<<8 for the 35 monomials
};

static constexpr Tab make_tab() {
    Tab t{};
    int c = 0;
    for (int p = 0; p < NM; p++)
        for (int q = p; q < NM; q++) {
            t.pq[c].x = (unsigned char)p;
            t.pq[c].y = (unsigned char)q;
            c++;
        }
    for (; c < NGRP * 32; c++) { t.pq[c].x = 0; t.pq[c].y = 0; }
    int m = 0;
    for (int i = 0; i < NVAR; i++)
        for (int j = i; j < NVAR; j++)
            for (int k = j; k < NVAR; k++) {
                t.ijk[m] = (ushort)(i | (j << 4) | (k << 8));
                m++;
            }
    return t;
}

__device__ const Tab g_tab = make_tab();

__global__ void __launch_bounds__(WPB * 32)
bihom_k3_kernel(const float* __restrict__ z_re,
                const float* __restrict__ z_im,
                float* __restrict__ out, int B)
{
    const int warp = threadIdx.x >> 5;
    const int lane = threadIdx.x & 31;
    const int row  = blockIdx.x * WPB + warp;

    __shared__ float2 szz[WPB][NM + 1];
    __shared__ float  sz[WPB][2][NVAR + 3];

    if (row >= B) return;   // one row per warp: whole warp exits together

    // stage 0: row inputs into smem (dynamic indexing for monomial table)
    if (lane < NVAR) {
        sz[warp][0][lane] = z_re[row * NVAR + lane];
        sz[warp][1][lane] = z_im[row * NVAR + lane];
    }
    __syncwarp();

    // stage 1: 35 complex monomials z_i z_j z_k into smem
    for (int mm = lane; mm < NM; mm += 32) {
        const unsigned v = g_tab.ijk[mm];
        const int i = v & 15, j = (v >> 4) & 15, k = (v >> 8) & 15;
        const float ar = sz[warp][0][i], ai = sz[warp][1][i];
        const float br = sz[warp][0][j], bi = sz[warp][1][j];
        const float cr = sz[warp][0][k], ci = sz[warp][1][k];
        const float tr = ar * br - ai * bi;
        const float ti = ar * bi + ai * br;
        szz[warp][mm] = make_float2(tr * cr - ti * ci, tr * ci + ti * cr);
    }
    __syncwarp();

    // stage 2: 630 pairs; each yields re (col s) and, if strict, im (col 630+s-p-1)
    float* __restrict__ orow  = out + (size_t)row * NCOL;        // re base
    float* __restrict__ orowi = orow + (NPAIR - 1);              // im base: +629, then +s-p
    const float2* zz = szz[warp];

    #pragma unroll
    for (int g = 0; g < NGRP; g++) {
        const int s = lane + 32 * g;                 // 32*g is an immediate
        if (g < NGRP - 1 || s < NPAIR) {
            const uchar2 t = g_tab.pq[s];
            const int p = t.x, q = t.y;
            const float2 a = zz[p];                  // broadcast within group
            const float2 b = zz[q];                  // consecutive q: conflict-free
            __stcs(orow + s, a.x * b.x + a.y * b.y); // re, coalesced
            if (q > p)                               // strict: emit im
                __stcs(orowi + (s - p), a.y * b.x - a.x * b.y);
        }
    }
}

extern "C" void kernel_launch(void* const* d_in, const int* in_sizes, int n_in,
                              void* d_out, int out_size) {
    const float* z_re = (const float*)d_in[0];
    const float* z_im = (const float*)d_in[1];
    float* out = (float*)d_out;
    const int B = in_sizes[0] / NVAR;
    const int grid = (B + WPB - 1) / WPB;
    bihom_k3_kernel<<<grid, WPB * 32>>>(z_re, z_im, out, B);
}

// round 4
// speedup vs baseline: 1.8187x; 1.0300x over previous
#include <cuda_runtime.h>
#include <cstdint>
#include <cstddef>

// Bihomogeneous_k3 — warp-per-row, fused re+im per pair, table-free indexing.
// (p,q) computed from pair index s via compile-time run breakpoints
// (off(p) = p*(71-p)/2), removing the per-group table LDG wavefront.

#define NVAR 5
#define NM 35
#define NPAIR 630
#define NCOL 1225
#define WPB 8
#define NGRP 20

__host__ __device__ constexpr int off_of(int p) { return p * (71 - p) / 2; }
__host__ __device__ constexpr int p_of(int s) {
    int p = 0;
    while (off_of(p + 1) <= s) p++;
    return p;
}

template<int... I> struct iseq {};
template<int N, int... I> struct make_iseq : make_iseq<N - 1, N - 1, I...> {};
template<int... I> struct make_iseq<0, I...> { using type = iseq<I...>; };

// p for pair index s within group G: pmin + count of breakpoints passed.
// All off_of(...) arguments are compile-time -> ISETP against immediates.
template<int PMIN, int... J>
__device__ __forceinline__ int p_from_s(int s, iseq<J...>) {
    int p = PMIN;
    ((p += (s >= off_of(PMIN + 1 + J)) ? 1 : 0), ...);
    return p;
}

template<int G>
__device__ __forceinline__ void do_group(const float2* __restrict__ zz,
                                         float* __restrict__ orow,
                                         float* __restrict__ orowi,
                                         int lane) {
    const int s = 32 * G + lane;
    if constexpr (32 * G + 31 >= NPAIR) {
        if (s >= NPAIR) return;           // only last (partial) group
    }
    constexpr int pmin = p_of(32 * G);
    constexpr int smax = (32 * G + 31 < NPAIR - 1) ? 32 * G + 31 : NPAIR - 1;
    constexpr int pmax = p_of(smax);

    const int p = p_from_s<pmin>(s, typename make_iseq<pmax - pmin>::type{});
    const int q = s + p - ((p * (71 - p)) >> 1);   // s - off(p) + p

    const float2 a = zz[p];                        // few distinct addrs -> 1 wf
    const float2 b = zz[q];                        // consecutive q -> 2 wf
    __stcs(orow + s, a.x * b.x + a.y * b.y);       // re(zz_p * conj(zz_q))
    if (q > p)                                     // strict pair -> im column
        __stcs(orowi + (s - p), a.y * b.x - a.x * b.y);
}

template<int... G>
__device__ __forceinline__ void all_groups(iseq<G...>, const float2* __restrict__ zz,
                                           float* __restrict__ orow,
                                           float* __restrict__ orowi, int lane) {
    (do_group<G>(zz, orow, orowi, lane), ...);
}

// monomial index table for stage 1 (2 warp-iterations, negligible traffic)
struct TabM { ushort ijk[40]; };
static constexpr TabM make_tabm() {
    TabM t{};
    int m = 0;
    for (int i = 0; i < NVAR; i++)
        for (int j = i; j < NVAR; j++)
            for (int k = j; k < NVAR; k++) {
                t.ijk[m] = (ushort)(i | (j << 4) | (k << 8));
                m++;
            }
    return t;
}
__device__ const TabM g_tabm = make_tabm();

__global__ void __launch_bounds__(WPB * 32)
bihom_k3_kernel(const float* __restrict__ z_re,
                const float* __restrict__ z_im,
                float* __restrict__ out, int B)
{
    const int warp = threadIdx.x >> 5;
    const int lane = threadIdx.x & 31;
    const int row  = blockIdx.x * WPB + warp;

    __shared__ float2 szz[WPB][NM + 1];
    __shared__ float  sz[WPB][2][NVAR + 3];

    if (row >= B) return;   // one row per warp: uniform exit

    // stage 0: row inputs into smem
    if (lane < NVAR) {
        sz[warp][0][lane] = z_re[row * NVAR + lane];
        sz[warp][1][lane] = z_im[row * NVAR + lane];
    }
    __syncwarp();

    // stage 1: 35 complex monomials z_i z_j z_k
    for (int mm = lane; mm < NM; mm += 32) {
        const unsigned v = g_tabm.ijk[mm];
        const int i = v & 15, j = (v >> 4) & 15, k = (v >> 8) & 15;
        const float ar = sz[warp][0][i], ai = sz[warp][1][i];
        const float br = sz[warp][0][j], bi = sz[warp][1][j];
        const float cr = sz[warp][0][k], ci = sz[warp][1][k];
        const float tr = ar * br - ai * bi;
        const float ti = ar * bi + ai * br;
        szz[warp][mm] = make_float2(tr * cr - ti * ci, tr * ci + ti * cr);
    }
    __syncwarp();

    // stage 2: 630 fused pair-products -> 1225 streaming stores
    float* __restrict__ orow  = out + (size_t)row * NCOL;
    float* __restrict__ orowi = orow + (NPAIR - 1);          // +629; im col = 629+s-p
    all_groups(typename make_iseq<NGRP>::type{}, szz[warp], orow, orowi, lane);
}

extern "C" void kernel_launch(void* const* d_in, const int* in_sizes, int n_in,
                              void* d_out, int out_size) {
    const float* z_re = (const float*)d_in[0];
    const float* z_im = (const float*)d_in[1];
    float* out = (float*)d_out;
    const int B = in_sizes[0] / NVAR;
    const int grid = (B + WPB - 1) / WPB;
    bihom_k3_kernel<<<grid, WPB * 32>>>(z_re, z_im, out, B);
}